// round 2
// baseline (speedup 1.0000x reference)
#include <cuda_runtime.h>
#include <cuda_bf16.h>
#include <math.h>

// Problem constants (match reference)
#define N_SRC0 100000
#define N_DST0 20000
#define N_DST1 4096
#define FDIM   256           // feature dim, floats
#define FDIM4  (FDIM/4)      // 64 float4s per row

// ---------------- device scratch (no allocations allowed) ----------------
__device__ float4 g_agg0[(size_t)N_DST0 * FDIM4];   // 20000 x 256 f32
__device__ float4 g_x   [(size_t)N_DST0 * FDIM4];   // layer0 output
__device__ float4 g_agg1[(size_t)N_DST1 * FDIM4];   // 4096 x 256 f32

__device__ int   g_deg_out0[N_SRC0];
__device__ int   g_deg_in0 [N_DST0];
__device__ int   g_deg_out1[N_DST0];
__device__ int   g_deg_in1 [N_DST1];

__device__ float g_nsrc0[N_SRC0];
__device__ float g_ndst0[N_DST0];
__device__ float g_nsrc1[N_DST0];
__device__ float g_ndst1[N_DST1];

// ---------------- zero all scratch ----------------
__global__ void zero_kernel() {
    const int tid = blockIdx.x * blockDim.x + threadIdx.x;
    const int stride = gridDim.x * blockDim.x;
    const float4 z4 = make_float4(0.f, 0.f, 0.f, 0.f);
    for (int i = tid; i < N_DST0 * FDIM4; i += stride) g_agg0[i] = z4;
    for (int i = tid; i < N_DST1 * FDIM4; i += stride) g_agg1[i] = z4;
    for (int i = tid; i < N_SRC0; i += stride) g_deg_out0[i] = 0;
    for (int i = tid; i < N_DST0; i += stride) { g_deg_in0[i] = 0; g_deg_out1[i] = 0; }
    for (int i = tid; i < N_DST1; i += stride) g_deg_in1[i] = 0;
}

// ---------------- degree counting ----------------
__global__ void deg_kernel(const int* __restrict__ src0, const int* __restrict__ dst0, int E0,
                           const int* __restrict__ src1, const int* __restrict__ dst1, int E1) {
    const int tid = blockIdx.x * blockDim.x + threadIdx.x;
    const int stride = gridDim.x * blockDim.x;
    for (int e = tid; e < E0; e += stride) {
        atomicAdd(&g_deg_out0[src0[e]], 1);
        atomicAdd(&g_deg_in0 [dst0[e]], 1);
    }
    for (int e = tid; e < E1; e += stride) {
        atomicAdd(&g_deg_out1[src1[e]], 1);
        atomicAdd(&g_deg_in1 [dst1[e]], 1);
    }
}

// ---------------- norms: clip(deg,1)^-0.5 ----------------
__global__ void norm_kernel() {
    const int i = blockIdx.x * blockDim.x + threadIdx.x;
    if (i < N_SRC0) g_nsrc0[i] = rsqrtf(fmaxf((float)g_deg_out0[i], 1.f));
    if (i < N_DST0) {
        g_ndst0[i] = rsqrtf(fmaxf((float)g_deg_in0 [i], 1.f));
        g_nsrc1[i] = rsqrtf(fmaxf((float)g_deg_out1[i], 1.f));
    }
    if (i < N_DST1) g_ndst1[i] = rsqrtf(fmaxf((float)g_deg_in1[i], 1.f));
}

// ---------------- vector red to global ----------------
__device__ __forceinline__ void red_add_v4(float4* addr, float4 v) {
    asm volatile("red.global.add.v4.f32 [%0], {%1, %2, %3, %4};"
                 :: "l"(addr), "f"(v.x), "f"(v.y), "f"(v.z), "f"(v.w)
                 : "memory");
}

// ---------------- edge aggregation: agg[dst] += nsrc[src] * feat[src] ----------------
// L=0: feat = features (param), nsrc = g_nsrc0, out = g_agg0
// L=1: feat = g_x,              nsrc = g_nsrc1, out = g_agg1
// 64 lanes (float4 each) per edge.
template <int L>
__global__ void agg_kernel(const int* __restrict__ src, const int* __restrict__ dst,
                           const float4* __restrict__ featExt, int E) {
    const long long idx = (long long)blockIdx.x * blockDim.x + threadIdx.x;
    const int e = (int)(idx >> 6);
    const int lane = (int)(idx & 63);
    if (e >= E) return;
    const float4* __restrict__ feat = (L == 0) ? featExt : (const float4*)g_x;
    const float*  __restrict__ nsrc = (L == 0) ? g_nsrc0 : g_nsrc1;
    float4* outp                    = (L == 0) ? g_agg0  : g_agg1;
    const int s = src[e];
    const int d = dst[e];
    const float ns = __ldg(&nsrc[s]);
    float4 v = feat[(size_t)s * FDIM4 + lane];
    v.x *= ns; v.y *= ns; v.z *= ns; v.w *= ns;
    red_add_v4(&outp[(size_t)d * FDIM4 + lane], v);
}

// ---------------- tiled SGEMM with row-scale + bias (+relu) epilogue ----------------
// C[m,n] = act( rowscale[m] * sum_k A[m,k]*B[k,n] + bias[n] )
// L=0: A = g_agg0 [20000,256], rowscale = g_ndst0, C = g_x, N=256, relu
// L=1: A = g_agg1 [4096,256],  rowscale = g_ndst1, C = Cext (d_out), N=128
// BM=BN=128, BK=8, 256 threads, 8x8 per thread.
template <int L>
__global__ __launch_bounds__(256)
void sgemm_kernel(const float* __restrict__ B, const float* __restrict__ bias,
                  float* __restrict__ Cext) {
    const int M = (L == 0) ? N_DST0 : N_DST1;
    const int N = (L == 0) ? 256 : 128;
    const int K = 256;
    const float* __restrict__ A        = (L == 0) ? (const float*)g_agg0 : (const float*)g_agg1;
    const float* __restrict__ rowscale = (L == 0) ? g_ndst0 : g_ndst1;
    float* __restrict__ C              = (L == 0) ? (float*)g_x : Cext;

    __shared__ float As[8][128];
    __shared__ float Bs[8][128];

    const int tid  = threadIdx.x;
    const int tcol = tid % 16;      // 16 thread-cols * TN=8 = 128
    const int trow = tid / 16;      // 16 thread-rows * TM=8 = 128
    const int rowBase = blockIdx.y * 128;
    const int colBase = blockIdx.x * 128;

    // A load mapping: one float4 per thread (128 rows x 8 k)
    const int aRow = tid >> 1;            // 0..127
    const int aK   = (tid & 1) * 4;       // 0 or 4
    // B load mapping: one float4 per thread (8 k x 128 cols)
    const int bK   = tid >> 5;            // 0..7
    const int bCol = (tid & 31) * 4;      // 0..124

    float acc[8][8];
#pragma unroll
    for (int i = 0; i < 8; i++)
#pragma unroll
        for (int j = 0; j < 8; j++) acc[i][j] = 0.f;

    for (int k0 = 0; k0 < K; k0 += 8) {
        const int gr = rowBase + aRow;
        float4 a4 = make_float4(0.f, 0.f, 0.f, 0.f);
        if (gr < M) a4 = *(const float4*)&A[(size_t)gr * K + k0 + aK];
        As[aK + 0][aRow] = a4.x;
        As[aK + 1][aRow] = a4.y;
        As[aK + 2][aRow] = a4.z;
        As[aK + 3][aRow] = a4.w;
        const float4 b4 = *(const float4*)&B[(size_t)(k0 + bK) * N + colBase + bCol];
        Bs[bK][bCol + 0] = b4.x;
        Bs[bK][bCol + 1] = b4.y;
        Bs[bK][bCol + 2] = b4.z;
        Bs[bK][bCol + 3] = b4.w;
        __syncthreads();

#pragma unroll
        for (int k = 0; k < 8; k++) {
            float ra[8], rb[8];
#pragma unroll
            for (int i = 0; i < 8; i++) ra[i] = As[k][trow * 8 + i];
#pragma unroll
            for (int j = 0; j < 8; j++) rb[j] = Bs[k][tcol * 8 + j];
#pragma unroll
            for (int i = 0; i < 8; i++)
#pragma unroll
                for (int j = 0; j < 8; j++) acc[i][j] = fmaf(ra[i], rb[j], acc[i][j]);
        }
        __syncthreads();
    }

#pragma unroll
    for (int i = 0; i < 8; i++) {
        const int row = rowBase + trow * 8 + i;
        if (row >= M) continue;
        const float rs = rowscale[row];
#pragma unroll
        for (int j = 0; j < 8; j++) {
            const int col = colBase + tcol * 8 + j;
            float v = fmaf(acc[i][j], rs, bias[col]);
            if (L == 0) v = fmaxf(v, 0.f);
            C[(size_t)row * N + col] = v;
        }
    }
}

// ---------------- launch ----------------
extern "C" void kernel_launch(void* const* d_in, const int* in_sizes, int n_in,
                              void* d_out, int out_size) {
    const float* features = (const float*)d_in[0];   // [100000, 256]
    const float* W1       = (const float*)d_in[1];   // [256, 256]
    const float* b1       = (const float*)d_in[2];   // [256]
    const float* W2       = (const float*)d_in[3];   // [256, 128]
    const float* b2       = (const float*)d_in[4];   // [128]
    const int*   src0     = (const int*)d_in[5];
    const int*   dst0     = (const int*)d_in[6];
    const int*   src1     = (const int*)d_in[7];
    const int*   dst1     = (const int*)d_in[8];
    const int E0 = in_sizes[5];
    const int E1 = in_sizes[7];
    float* out = (float*)d_out;                       // [4096, 128]

    // 1) zero scratch
    zero_kernel<<<2048, 256>>>();

    // 2) degrees
    deg_kernel<<<1024, 256>>>(src0, dst0, E0, src1, dst1, E1);

    // 3) norms
    norm_kernel<<<(N_SRC0 + 255) / 256, 256>>>();

    // 4) layer-0 aggregation
    {
        long long threads = (long long)E0 * 64;
        int blocks = (int)((threads + 255) / 256);
        agg_kernel<0><<<blocks, 256>>>(src0, dst0, (const float4*)features, E0);
    }

    // 5) layer-0 dense: x = relu((agg0 * ndst0) @ W1 + b1)
    {
        dim3 grid(256 / 128, (N_DST0 + 127) / 128);
        sgemm_kernel<0><<<grid, 256>>>(W1, b1, nullptr);
    }

    // 6) layer-1 aggregation
    {
        long long threads = (long long)E1 * 64;
        int blocks = (int)((threads + 255) / 256);
        agg_kernel<1><<<blocks, 256>>>(src1, dst1, nullptr, E1);
    }

    // 7) layer-1 dense: out = (agg1 * ndst1) @ W2 + b2
    {
        dim3 grid(128 / 128, (N_DST1 + 127) / 128);
        sgemm_kernel<1><<<grid, 256>>>(W2, b2, out);
    }
}

// round 4
// speedup vs baseline: 1.1725x; 1.1725x over previous
#include <cuda_runtime.h>
#include <cuda_bf16.h>
#include <math.h>

// Problem constants (match reference)
#define N_SRC0 100000
#define N_DST0 20000
#define N_DST1 4096
#define FDIM   256           // feature dim, floats
#define FDIM4  (FDIM/4)      // 64 float4s per row

// ---------------- device scratch (no allocations allowed) ----------------
__device__ float4 g_agg0[(size_t)N_DST0 * FDIM4];   // 20000 x 256 f32
__device__ float4 g_x   [(size_t)N_DST0 * FDIM4];   // layer0 output
__device__ float4 g_agg1[(size_t)N_DST1 * FDIM4];   // 4096 x 256 f32

__device__ int   g_deg_out0[N_SRC0];
__device__ int   g_deg_in0 [N_DST0];
__device__ int   g_deg_out1[N_DST0];
__device__ int   g_deg_in1 [N_DST1];

__device__ float g_nsrc0[N_SRC0];
__device__ float g_ndst0[N_DST0];
__device__ float g_nsrc1[N_DST0];
__device__ float g_ndst1[N_DST1];

// ---------------- zero all scratch ----------------
__global__ void zero_kernel() {
    const int tid = blockIdx.x * blockDim.x + threadIdx.x;
    const int stride = gridDim.x * blockDim.x;
    const float4 z4 = make_float4(0.f, 0.f, 0.f, 0.f);
    for (int i = tid; i < N_DST0 * FDIM4; i += stride) g_agg0[i] = z4;
    for (int i = tid; i < N_DST1 * FDIM4; i += stride) g_agg1[i] = z4;
    for (int i = tid; i < N_SRC0; i += stride) g_deg_out0[i] = 0;
    for (int i = tid; i < N_DST0; i += stride) { g_deg_in0[i] = 0; g_deg_out1[i] = 0; }
    for (int i = tid; i < N_DST1; i += stride) g_deg_in1[i] = 0;
}

// ---------------- degree counting ----------------
__global__ void deg_kernel(const int* __restrict__ src0, const int* __restrict__ dst0, int E0,
                           const int* __restrict__ src1, const int* __restrict__ dst1, int E1) {
    const int tid = blockIdx.x * blockDim.x + threadIdx.x;
    const int stride = gridDim.x * blockDim.x;
    for (int e = tid; e < E0; e += stride) {
        atomicAdd(&g_deg_out0[src0[e]], 1);
        atomicAdd(&g_deg_in0 [dst0[e]], 1);
    }
    for (int e = tid; e < E1; e += stride) {
        atomicAdd(&g_deg_out1[src1[e]], 1);
        atomicAdd(&g_deg_in1 [dst1[e]], 1);
    }
}

// ---------------- norms: clip(deg,1)^-0.5 ----------------
__global__ void norm_kernel() {
    const int i = blockIdx.x * blockDim.x + threadIdx.x;
    if (i < N_SRC0) g_nsrc0[i] = rsqrtf(fmaxf((float)g_deg_out0[i], 1.f));
    if (i < N_DST0) {
        g_ndst0[i] = rsqrtf(fmaxf((float)g_deg_in0 [i], 1.f));
        g_nsrc1[i] = rsqrtf(fmaxf((float)g_deg_out1[i], 1.f));
    }
    if (i < N_DST1) g_ndst1[i] = rsqrtf(fmaxf((float)g_deg_in1[i], 1.f));
}

// ---------------- vector red to global ----------------
__device__ __forceinline__ void red_add_v4(float4* addr, float4 v) {
    asm volatile("red.global.add.v4.f32 [%0], {%1, %2, %3, %4};"
                 :: "l"(addr), "f"(v.x), "f"(v.y), "f"(v.z), "f"(v.w)
                 : "memory");
}

// ---------------- packed f32x2 helpers ----------------
__device__ __forceinline__ unsigned long long pack2(float lo, float hi) {
    unsigned long long r;
    asm("mov.b64 %0, {%1, %2};" : "=l"(r) : "f"(lo), "f"(hi));
    return r;
}
__device__ __forceinline__ void unpack2(unsigned long long v, float& lo, float& hi) {
    asm("mov.b64 {%0, %1}, %2;" : "=f"(lo), "=f"(hi) : "l"(v));
}
__device__ __forceinline__ unsigned long long fma2(unsigned long long a,
                                                   unsigned long long b,
                                                   unsigned long long c) {
    unsigned long long d;
    asm("fma.rn.f32x2 %0, %1, %2, %3;" : "=l"(d) : "l"(a), "l"(b), "l"(c));
    return d;
}

// ---------------- edge aggregation: agg[dst] += nsrc[src] * feat[src] ----------------
// 64 lanes (float4 each) per edge, EPT=4 edges per thread for MLP.
#define EPT 4
template <int L>
__global__ void agg_kernel(const int* __restrict__ src, const int* __restrict__ dst,
                           const float4* __restrict__ featExt, int E) {
    const float4* __restrict__ feat = (L == 0) ? featExt : (const float4*)g_x;
    const float*  __restrict__ nsrc = (L == 0) ? g_nsrc0 : g_nsrc1;
    float4* outp                    = (L == 0) ? g_agg0  : g_agg1;

    const long long idx = (long long)blockIdx.x * blockDim.x + threadIdx.x;
    const int lane  = (int)(idx & 63);
    const int eBase = (int)(idx >> 6) * EPT;
    if (eBase >= E) return;

    int s[EPT], d[EPT];
    float ns[EPT];
    float4 v[EPT];
    const int cnt = min(EPT, E - eBase);

    // batch index loads (independent)
#pragma unroll
    for (int q = 0; q < EPT; q++) {
        const int e = (q < cnt) ? (eBase + q) : eBase;
        s[q] = src[e];
        d[q] = dst[e];
    }
    // batch norm loads
#pragma unroll
    for (int q = 0; q < EPT; q++) ns[q] = __ldg(&nsrc[s[q]]);
    // batch feature loads (4 independent LDG.128 in flight)
#pragma unroll
    for (int q = 0; q < EPT; q++) v[q] = feat[(size_t)s[q] * FDIM4 + lane];
    // scale + scatter
#pragma unroll
    for (int q = 0; q < EPT; q++) {
        if (q < cnt) {
            const float n = ns[q];
            float4 w = v[q];
            w.x *= n; w.y *= n; w.z *= n; w.w *= n;
            red_add_v4(&outp[(size_t)d[q] * FDIM4 + lane], w);
        }
    }
}

// ---------------- tiled SGEMM (f32x2 packed) with row-scale + bias (+relu) ----------------
// C[m,n] = act( rowscale[m] * sum_k A[m,k]*B[k,n] + bias[n] )
// L=0: A=g_agg0 [20000,256], rs=g_ndst0, C=g_x, N=256, relu
// L=1: A=g_agg1 [4096,256],  rs=g_ndst1, C=Cext, N=128
// BM=BN=128, BK=8, 256 threads, 8x8 per thread (as 8x4 f32x2 pairs).
template <int L>
__global__ __launch_bounds__(256)
void sgemm_kernel(const float* __restrict__ B, const float* __restrict__ bias,
                  float* __restrict__ Cext) {
    const int M = (L == 0) ? N_DST0 : N_DST1;
    const int N = (L == 0) ? 256 : 128;
    const int K = 256;
    const float* __restrict__ A        = (L == 0) ? (const float*)g_agg0 : (const float*)g_agg1;
    const float* __restrict__ rowscale = (L == 0) ? g_ndst0 : g_ndst1;
    float* __restrict__ C              = (L == 0) ? (float*)g_x : Cext;

    __shared__ float As[8][128];
    __shared__ float Bs[8][128];

    const int tid  = threadIdx.x;
    const int tcol = tid % 16;      // 16 thread-cols * 8 = 128
    const int trow = tid / 16;      // 16 thread-rows * 8 = 128
    const int rowBase = blockIdx.y * 128;
    const int colBase = blockIdx.x * 128;

    const int aRow = tid >> 1;            // 0..127
    const int aK   = (tid & 1) * 4;       // 0 or 4
    const int bK   = tid >> 5;            // 0..7
    const int bCol = (tid & 31) * 4;      // 0..124

    unsigned long long acc2[8][4];
    const unsigned long long z2 = pack2(0.f, 0.f);
#pragma unroll
    for (int i = 0; i < 8; i++)
#pragma unroll
        for (int j = 0; j < 4; j++) acc2[i][j] = z2;

    for (int k0 = 0; k0 < K; k0 += 8) {
        const int gr = rowBase + aRow;
        float4 a4 = make_float4(0.f, 0.f, 0.f, 0.f);
        if (gr < M) a4 = *(const float4*)&A[(size_t)gr * K + k0 + aK];
        As[aK + 0][aRow] = a4.x;
        As[aK + 1][aRow] = a4.y;
        As[aK + 2][aRow] = a4.z;
        As[aK + 3][aRow] = a4.w;
        *(float4*)&Bs[bK][bCol] = *(const float4*)&B[(size_t)(k0 + bK) * N + colBase + bCol];
        __syncthreads();

#pragma unroll
        for (int k = 0; k < 8; k++) {
            const float4 a0 = *(const float4*)&As[k][trow * 8];
            const float4 a1 = *(const float4*)&As[k][trow * 8 + 4];
            const float4 b0 = *(const float4*)&Bs[k][tcol * 8];
            const float4 b1 = *(const float4*)&Bs[k][tcol * 8 + 4];
            unsigned long long rb2[4];
            rb2[0] = pack2(b0.x, b0.y);
            rb2[1] = pack2(b0.z, b0.w);
            rb2[2] = pack2(b1.x, b1.y);
            rb2[3] = pack2(b1.z, b1.w);
            const float ra[8] = {a0.x, a0.y, a0.z, a0.w, a1.x, a1.y, a1.z, a1.w};
#pragma unroll
            for (int i = 0; i < 8; i++) {
                const unsigned long long a2 = pack2(ra[i], ra[i]);
#pragma unroll
                for (int j = 0; j < 4; j++) acc2[i][j] = fma2(a2, rb2[j], acc2[i][j]);
            }
        }
        __syncthreads();
    }

    // epilogue: rowscale, bias, optional relu
#pragma unroll
    for (int i = 0; i < 8; i++) {
        const int row = rowBase + trow * 8 + i;
        if (row >= M) continue;
        const float rs = rowscale[row];
#pragma unroll
        for (int j = 0; j < 4; j++) {
            float lo, hi;
            unpack2(acc2[i][j], lo, hi);
            const int col = colBase + tcol * 8 + j * 2;
            float v0 = fmaf(lo, rs, bias[col]);
            float v1 = fmaf(hi, rs, bias[col + 1]);
            if (L == 0) { v0 = fmaxf(v0, 0.f); v1 = fmaxf(v1, 0.f); }
            C[(size_t)row * N + col]     = v0;
            C[(size_t)row * N + col + 1] = v1;
        }
    }
}

// ---------------- launch ----------------
extern "C" void kernel_launch(void* const* d_in, const int* in_sizes, int n_in,
                              void* d_out, int out_size) {
    const float* features = (const float*)d_in[0];   // [100000, 256]
    const float* W1       = (const float*)d_in[1];   // [256, 256]
    const float* b1       = (const float*)d_in[2];   // [256]
    const float* W2       = (const float*)d_in[3];   // [256, 128]
    const float* b2       = (const float*)d_in[4];   // [128]
    const int*   src0     = (const int*)d_in[5];
    const int*   dst0     = (const int*)d_in[6];
    const int*   src1     = (const int*)d_in[7];
    const int*   dst1     = (const int*)d_in[8];
    const int E0 = in_sizes[5];
    const int E1 = in_sizes[7];
    float* out = (float*)d_out;                       // [4096, 128]

    // 1) zero scratch
    zero_kernel<<<2048, 256>>>();

    // 2) degrees
    deg_kernel<<<1024, 256>>>(src0, dst0, E0, src1, dst1, E1);

    // 3) norms
    norm_kernel<<<(N_SRC0 + 255) / 256, 256>>>();

    // 4) layer-0 aggregation
    {
        long long threads = ((long long)(E0 + EPT - 1) / EPT) * 64;
        int blocks = (int)((threads + 255) / 256);
        agg_kernel<0><<<blocks, 256>>>(src0, dst0, (const float4*)features, E0);
    }

    // 5) layer-0 dense: x = relu((agg0 * ndst0) @ W1 + b1)
    {
        dim3 grid(256 / 128, (N_DST0 + 127) / 128);
        sgemm_kernel<0><<<grid, 256>>>(W1, b1, nullptr);
    }

    // 6) layer-1 aggregation
    {
        long long threads = ((long long)(E1 + EPT - 1) / EPT) * 64;
        int blocks = (int)((threads + 255) / 256);
        agg_kernel<1><<<blocks, 256>>>(src1, dst1, nullptr, E1);
    }

    // 7) layer-1 dense: out = (agg1 * ndst1) @ W2 + b2
    {
        dim3 grid(128 / 128, (N_DST1 + 127) / 128);
        sgemm_kernel<1><<<grid, 256>>>(W2, b2, out);
    }
}

// round 5
// speedup vs baseline: 1.3269x; 1.1317x over previous
#include <cuda_runtime.h>
#include <cuda_bf16.h>
#include <math.h>

// Problem constants (match reference)
#define N_SRC0 100000
#define N_DST0 20000
#define N_DST1 4096
#define FDIM   256           // feature dim, floats
#define FDIM4  (FDIM/4)      // 64 float4s per row
#define E0_MAX 640000
#define E1_MAX 131072

// ---------------- device scratch (no allocations allowed) ----------------
__device__ float4 g_agg0[(size_t)N_DST0 * FDIM4];   // 20000 x 256 f32
__device__ float4 g_x   [(size_t)N_DST0 * FDIM4];   // layer0 output
__device__ float4 g_agg1[(size_t)N_DST1 * FDIM4];   // 4096 x 256 f32

__device__ int   g_deg_out0[N_SRC0];
__device__ int   g_deg_in0 [N_DST0];
__device__ int   g_deg_out1[N_DST0];
__device__ int   g_deg_in1 [N_DST1];

__device__ float g_nsrc0[N_SRC0];
__device__ float g_ndst0[N_DST0];
__device__ float g_nsrc1[N_DST0];
__device__ float g_ndst1[N_DST1];

// CSR (dst-sorted edge lists)
__device__ int g_row0[N_DST0 + 1];
__device__ int g_cur0[N_DST0];
__device__ int g_eidx0[E0_MAX];      // src id per slot
__device__ int g_row1[N_DST1 + 1];
__device__ int g_cur1[N_DST1];
__device__ int g_eidx1[E1_MAX];

// ---------------- zero small scratch (deg arrays only) ----------------
__global__ void zero_kernel() {
    const int tid = blockIdx.x * blockDim.x + threadIdx.x;
    const int stride = gridDim.x * blockDim.x;
    for (int i = tid; i < N_SRC0; i += stride) g_deg_out0[i] = 0;
    for (int i = tid; i < N_DST0; i += stride) { g_deg_in0[i] = 0; g_deg_out1[i] = 0; }
    for (int i = tid; i < N_DST1; i += stride) g_deg_in1[i] = 0;
}

// ---------------- degree counting ----------------
__global__ void deg_kernel(const int* __restrict__ src0, const int* __restrict__ dst0, int E0,
                           const int* __restrict__ src1, const int* __restrict__ dst1, int E1) {
    const int tid = blockIdx.x * blockDim.x + threadIdx.x;
    const int stride = gridDim.x * blockDim.x;
    for (int e = tid; e < E0; e += stride) {
        atomicAdd(&g_deg_out0[src0[e]], 1);
        atomicAdd(&g_deg_in0 [dst0[e]], 1);
    }
    for (int e = tid; e < E1; e += stride) {
        atomicAdd(&g_deg_out1[src1[e]], 1);
        atomicAdd(&g_deg_in1 [dst1[e]], 1);
    }
}

// ---------------- norms: clip(deg,1)^-0.5 ----------------
__global__ void norm_kernel() {
    const int i = blockIdx.x * blockDim.x + threadIdx.x;
    if (i < N_SRC0) g_nsrc0[i] = rsqrtf(fmaxf((float)g_deg_out0[i], 1.f));
    if (i < N_DST0) {
        g_ndst0[i] = rsqrtf(fmaxf((float)g_deg_in0 [i], 1.f));
        g_nsrc1[i] = rsqrtf(fmaxf((float)g_deg_out1[i], 1.f));
    }
    if (i < N_DST1) g_ndst1[i] = rsqrtf(fmaxf((float)g_deg_in1[i], 1.f));
}

// ---------------- exclusive prefix scan of deg_in -> row offsets (one block) ----------------
// Two-level: per-thread serial sum over a contiguous chunk, one block scan, then
// per-thread serial prefix rewrite. 1024 threads; PER0=20 covers 20480>=20000.
__global__ __launch_bounds__(1024) void scan_kernel() {
    __shared__ int sh[1024];
    const int t = threadIdx.x;

    // ----- layer 0 -----
    {
        const int PER = 20;
        const int base = t * PER;
        int sum = 0;
        for (int i = 0; i < PER; i++) {
            const int idx = base + i;
            if (idx < N_DST0) sum += g_deg_in0[idx];
        }
        sh[t] = sum; __syncthreads();
        for (int off = 1; off < 1024; off <<= 1) {
            const int v = (t >= off) ? sh[t - off] : 0;
            __syncthreads();
            sh[t] += v;
            __syncthreads();
        }
        int run = (t == 0) ? 0 : sh[t - 1];
        for (int i = 0; i < PER; i++) {
            const int idx = base + i;
            if (idx < N_DST0) {
                g_row0[idx] = run;
                g_cur0[idx] = run;
                run += g_deg_in0[idx];
            }
        }
        if (t == 1023) g_row0[N_DST0] = sh[1023];
        __syncthreads();
    }

    // ----- layer 1 -----
    {
        const int PER = 4;          // 1024*4 = 4096
        const int base = t * PER;
        int sum = 0;
        for (int i = 0; i < PER; i++) sum += g_deg_in1[base + i];
        sh[t] = sum; __syncthreads();
        for (int off = 1; off < 1024; off <<= 1) {
            const int v = (t >= off) ? sh[t - off] : 0;
            __syncthreads();
            sh[t] += v;
            __syncthreads();
        }
        int run = (t == 0) ? 0 : sh[t - 1];
        for (int i = 0; i < PER; i++) {
            const int idx = base + i;
            g_row1[idx] = run;
            g_cur1[idx] = run;
            run += g_deg_in1[idx];
        }
        if (t == 1023) g_row1[N_DST1] = sh[1023];
    }
}

// ---------------- fill CSR slots (counting sort by dst) ----------------
__global__ void fill_kernel(const int* __restrict__ src0, const int* __restrict__ dst0, int E0,
                            const int* __restrict__ src1, const int* __restrict__ dst1, int E1) {
    const int tid = blockIdx.x * blockDim.x + threadIdx.x;
    const int stride = gridDim.x * blockDim.x;
    for (int e = tid; e < E0; e += stride) {
        const int pos = atomicAdd(&g_cur0[dst0[e]], 1);
        g_eidx0[pos] = src0[e];
    }
    for (int e = tid; e < E1; e += stride) {
        const int pos = atomicAdd(&g_cur1[dst1[e]], 1);
        g_eidx1[pos] = src1[e];
    }
}

// ---------------- gather aggregation: agg[r] = sum_{e in row r} nsrc[src_e]*feat[src_e] ----------------
// 64 threads per row (one float4 lane each), 4 rows per 256-thread block.
// No atomics; each output element written exactly once.
template <int L>
__global__ __launch_bounds__(256) void agg_gather_kernel(const float4* __restrict__ featExt) {
    const float4* __restrict__ feat = (L == 0) ? featExt : (const float4*)g_x;
    const float*  __restrict__ nsrc = (L == 0) ? g_nsrc0 : g_nsrc1;
    const int*    __restrict__ rowo = (L == 0) ? g_row0  : g_row1;
    const int*    __restrict__ eidx = (L == 0) ? g_eidx0 : g_eidx1;
    float4* outp                    = (L == 0) ? g_agg0  : g_agg1;
    const int nRows                 = (L == 0) ? N_DST0  : N_DST1;

    const int lane = threadIdx.x & 63;
    const int row  = blockIdx.x * 4 + (threadIdx.x >> 6);
    if (row >= nRows) return;

    const int beg = rowo[row];
    const int end = rowo[row + 1];

    float4 acc = make_float4(0.f, 0.f, 0.f, 0.f);
    int e = beg;
    // unrolled by 4 for MLP
    for (; e + 4 <= end; e += 4) {
        const int s0 = eidx[e + 0];
        const int s1 = eidx[e + 1];
        const int s2 = eidx[e + 2];
        const int s3 = eidx[e + 3];
        const float n0 = __ldg(&nsrc[s0]);
        const float n1 = __ldg(&nsrc[s1]);
        const float n2 = __ldg(&nsrc[s2]);
        const float n3 = __ldg(&nsrc[s3]);
        const float4 v0 = feat[(size_t)s0 * FDIM4 + lane];
        const float4 v1 = feat[(size_t)s1 * FDIM4 + lane];
        const float4 v2 = feat[(size_t)s2 * FDIM4 + lane];
        const float4 v3 = feat[(size_t)s3 * FDIM4 + lane];
        acc.x += n0 * v0.x; acc.y += n0 * v0.y; acc.z += n0 * v0.z; acc.w += n0 * v0.w;
        acc.x += n1 * v1.x; acc.y += n1 * v1.y; acc.z += n1 * v1.z; acc.w += n1 * v1.w;
        acc.x += n2 * v2.x; acc.y += n2 * v2.y; acc.z += n2 * v2.z; acc.w += n2 * v2.w;
        acc.x += n3 * v3.x; acc.y += n3 * v3.y; acc.z += n3 * v3.z; acc.w += n3 * v3.w;
    }
    for (; e < end; e++) {
        const int s = eidx[e];
        const float n = __ldg(&nsrc[s]);
        const float4 v = feat[(size_t)s * FDIM4 + lane];
        acc.x += n * v.x; acc.y += n * v.y; acc.z += n * v.z; acc.w += n * v.w;
    }
    outp[(size_t)row * FDIM4 + lane] = acc;
}

// ---------------- packed f32x2 helpers ----------------
__device__ __forceinline__ unsigned long long pack2(float lo, float hi) {
    unsigned long long r;
    asm("mov.b64 %0, {%1, %2};" : "=l"(r) : "f"(lo), "f"(hi));
    return r;
}
__device__ __forceinline__ void unpack2(unsigned long long v, float& lo, float& hi) {
    asm("mov.b64 {%0, %1}, %2;" : "=f"(lo), "=f"(hi) : "l"(v));
}
__device__ __forceinline__ unsigned long long fma2(unsigned long long a,
                                                   unsigned long long b,
                                                   unsigned long long c) {
    unsigned long long d;
    asm("fma.rn.f32x2 %0, %1, %2, %3;" : "=l"(d) : "l"(a), "l"(b), "l"(c));
    return d;
}

// ---------------- tiled SGEMM (f32x2 packed) with row-scale + bias (+relu) ----------------
// C[m,n] = act( rowscale[m] * sum_k A[m,k]*B[k,n] + bias[n] )
template <int L>
__global__ __launch_bounds__(256)
void sgemm_kernel(const float* __restrict__ B, const float* __restrict__ bias,
                  float* __restrict__ Cext) {
    const int M = (L == 0) ? N_DST0 : N_DST1;
    const int N = (L == 0) ? 256 : 128;
    const int K = 256;
    const float* __restrict__ A        = (L == 0) ? (const float*)g_agg0 : (const float*)g_agg1;
    const float* __restrict__ rowscale = (L == 0) ? g_ndst0 : g_ndst1;
    float* __restrict__ C              = (L == 0) ? (float*)g_x : Cext;

    __shared__ float As[8][128];
    __shared__ float Bs[8][128];

    const int tid  = threadIdx.x;
    const int tcol = tid % 16;
    const int trow = tid / 16;
    const int rowBase = blockIdx.y * 128;
    const int colBase = blockIdx.x * 128;

    const int aRow = tid >> 1;
    const int aK   = (tid & 1) * 4;
    const int bK   = tid >> 5;
    const int bCol = (tid & 31) * 4;

    unsigned long long acc2[8][4];
    const unsigned long long z2 = pack2(0.f, 0.f);
#pragma unroll
    for (int i = 0; i < 8; i++)
#pragma unroll
        for (int j = 0; j < 4; j++) acc2[i][j] = z2;

    for (int k0 = 0; k0 < K; k0 += 8) {
        const int gr = rowBase + aRow;
        float4 a4 = make_float4(0.f, 0.f, 0.f, 0.f);
        if (gr < M) a4 = *(const float4*)&A[(size_t)gr * K + k0 + aK];
        As[aK + 0][aRow] = a4.x;
        As[aK + 1][aRow] = a4.y;
        As[aK + 2][aRow] = a4.z;
        As[aK + 3][aRow] = a4.w;
        *(float4*)&Bs[bK][bCol] = *(const float4*)&B[(size_t)(k0 + bK) * N + colBase + bCol];
        __syncthreads();

#pragma unroll
        for (int k = 0; k < 8; k++) {
            const float4 a0 = *(const float4*)&As[k][trow * 8];
            const float4 a1 = *(const float4*)&As[k][trow * 8 + 4];
            const float4 b0 = *(const float4*)&Bs[k][tcol * 8];
            const float4 b1 = *(const float4*)&Bs[k][tcol * 8 + 4];
            unsigned long long rb2[4];
            rb2[0] = pack2(b0.x, b0.y);
            rb2[1] = pack2(b0.z, b0.w);
            rb2[2] = pack2(b1.x, b1.y);
            rb2[3] = pack2(b1.z, b1.w);
            const float ra[8] = {a0.x, a0.y, a0.z, a0.w, a1.x, a1.y, a1.z, a1.w};
#pragma unroll
            for (int i = 0; i < 8; i++) {
                const unsigned long long a2 = pack2(ra[i], ra[i]);
#pragma unroll
                for (int j = 0; j < 4; j++) acc2[i][j] = fma2(a2, rb2[j], acc2[i][j]);
            }
        }
        __syncthreads();
    }

#pragma unroll
    for (int i = 0; i < 8; i++) {
        const int row = rowBase + trow * 8 + i;
        if (row >= M) continue;
        const float rs = rowscale[row];
#pragma unroll
        for (int j = 0; j < 4; j++) {
            float lo, hi;
            unpack2(acc2[i][j], lo, hi);
            const int col = colBase + tcol * 8 + j * 2;
            float v0 = fmaf(lo, rs, bias[col]);
            float v1 = fmaf(hi, rs, bias[col + 1]);
            if (L == 0) { v0 = fmaxf(v0, 0.f); v1 = fmaxf(v1, 0.f); }
            C[(size_t)row * N + col]     = v0;
            C[(size_t)row * N + col + 1] = v1;
        }
    }
}

// ---------------- launch ----------------
extern "C" void kernel_launch(void* const* d_in, const int* in_sizes, int n_in,
                              void* d_out, int out_size) {
    const float* features = (const float*)d_in[0];   // [100000, 256]
    const float* W1       = (const float*)d_in[1];   // [256, 256]
    const float* b1       = (const float*)d_in[2];   // [256]
    const float* W2       = (const float*)d_in[3];   // [256, 128]
    const float* b2       = (const float*)d_in[4];   // [128]
    const int*   src0     = (const int*)d_in[5];
    const int*   dst0     = (const int*)d_in[6];
    const int*   src1     = (const int*)d_in[7];
    const int*   dst1     = (const int*)d_in[8];
    const int E0 = in_sizes[5];
    const int E1 = in_sizes[7];
    float* out = (float*)d_out;                       // [4096, 128]

    // 1) zero small scratch (deg arrays)
    zero_kernel<<<512, 256>>>();

    // 2) degrees
    deg_kernel<<<1024, 256>>>(src0, dst0, E0, src1, dst1, E1);

    // 3) norms
    norm_kernel<<<(N_SRC0 + 255) / 256, 256>>>();

    // 4) CSR build: row offsets + slot fill
    scan_kernel<<<1, 1024>>>();
    fill_kernel<<<1024, 256>>>(src0, dst0, E0, src1, dst1, E1);

    // 5) layer-0 aggregation (gather, no atomics)
    agg_gather_kernel<0><<<(N_DST0 + 3) / 4, 256>>>((const float4*)features);

    // 6) layer-0 dense: x = relu((agg0 * ndst0) @ W1 + b1)
    {
        dim3 grid(256 / 128, (N_DST0 + 127) / 128);
        sgemm_kernel<0><<<grid, 256>>>(W1, b1, nullptr);
    }

    // 7) layer-1 aggregation (gather)
    agg_gather_kernel<1><<<(N_DST1 + 3) / 4, 256>>>(nullptr);

    // 8) layer-1 dense: out = (agg1 * ndst1) @ W2 + b2
    {
        dim3 grid(128 / 128, (N_DST1 + 127) / 128);
        sgemm_kernel<1><<<grid, 256>>>(W2, b2, out);
    }
}